// round 5
// baseline (speedup 1.0000x reference)
#include <cuda_runtime.h>

#define NN 4096
#define DD 70
#define BI 64          // output rows per block
#define BK 32          // K-chunk
#define TPB 256
#define ASTRIDE 65     // a_tile row stride (conflict-free)
#define SSTRIDE 72     // s_tile row stride

// Single kernel, two roles:
//   blocks [0, 64):   s_in[j,d]  = sum_i (adj[i,j,0]+adj[i,j,1]) * s[i,d]
//   blocks [64, 128): s_out[i,d] = sum_j (adj[i,j,0]+adj[i,j,1]) * s[j,d]
// Both roles reduce to C[64][70] = A_tile-K-major GEMM with identical inner loop.
__global__ __launch_bounds__(TPB, 1)
void slayer_kernel(const float* __restrict__ adj,
                   const float* __restrict__ s,
                   float* __restrict__ out)
{
    __shared__ float a_tile[BK][ASTRIDE];        // [k][row]
    __shared__ float s_tile[BK + 1][SSTRIDE];    // [k][d] (+1 row guard for padded reads)

    const int bid    = blockIdx.x;
    const int nrb    = NN / BI;                  // 64
    const bool do_out = (bid >= nrb);
    const int rb     = (do_out ? bid - nrb : bid) * BI;  // output row base

    const int tid = threadIdx.x;
    const int ty  = tid >> 4;    // 0..15 -> row group (4 rows each)
    const int tx  = tid & 15;    // 0..15 -> col group (cols tx+16c)

    float acc[4][5];
#pragma unroll
    for (int r = 0; r < 4; r++)
#pragma unroll
        for (int c = 0; c < 5; c++) acc[r][c] = 0.0f;

    for (int kc = 0; kc < NN; kc += BK) {
        // ---- load adj tile (channel-sum fused), K-major into a_tile[k][row] ----
        if (do_out) {
            // rows = i in [rb, rb+64), k = j in [kc, kc+32)
#pragma unroll
            for (int t = 0; t < (BI * BK) / TPB; t++) {
                int e   = tid + t * TPB;
                int i_l = e >> 5;      // 0..63
                int j_l = e & 31;      // 0..31
                const float2 v = *(const float2*)(adj +
                    ((size_t)(rb + i_l) * NN + (size_t)(kc + j_l)) * 2);
                a_tile[j_l][i_l] = v.x + v.y;   // bank = (j_l + i_l) % 32: conflict-free
            }
        } else {
            // rows = j in [rb, rb+64), k = i in [kc, kc+32)
#pragma unroll
            for (int t = 0; t < (BI * BK) / TPB; t++) {
                int e   = tid + t * TPB;
                int i_l = e >> 6;      // 0..31
                int j_l = e & 63;      // 0..63
                const float2 v = *(const float2*)(adj +
                    ((size_t)(kc + i_l) * NN + (size_t)(rb + j_l)) * 2);
                a_tile[i_l][j_l] = v.x + v.y;   // consecutive lanes -> consecutive banks
            }
        }
        // ---- load s tile: s[kc+k][d] ----
#pragma unroll
        for (int t = 0; t < (BK * DD + TPB - 1) / TPB; t++) {
            int e = tid + t * TPB;
            if (e < BK * DD) {
                int kk = e / DD;
                int d  = e - kk * DD;
                s_tile[kk][d] = s[(size_t)(kc + kk) * DD + d];
            }
        }
        __syncthreads();

        // ---- inner GEMM: 4x5 register tile per thread ----
#pragma unroll 8
        for (int kk = 0; kk < BK; kk++) {
            float av[4];
#pragma unroll
            for (int r = 0; r < 4; r++) av[r] = a_tile[kk][ty * 4 + r];
            float sv[5];
#pragma unroll
            for (int c = 0; c < 5; c++) sv[c] = s_tile[kk][tx + 16 * c];
#pragma unroll
            for (int r = 0; r < 4; r++)
#pragma unroll
                for (int c = 0; c < 5; c++)
                    acc[r][c] = fmaf(av[r], sv[c], acc[r][c]);
        }
        __syncthreads();
    }

    // ---- store: s_in at offset 0, s_out at N*D (tuple order (s_in, s_out)) ----
    float* dst = out + (do_out ? (size_t)NN * DD : 0);
#pragma unroll
    for (int r = 0; r < 4; r++) {
        int row = rb + ty * 4 + r;
#pragma unroll
        for (int c = 0; c < 5; c++) {
            int col = tx + 16 * c;
            if (col < DD) dst[(size_t)row * DD + col] = acc[r][c];
        }
    }
}

extern "C" void kernel_launch(void* const* d_in, const int* in_sizes, int n_in,
                              void* d_out, int out_size)
{
    const float* adj = (const float*)d_in[0];
    const float* s   = (const float*)d_in[1];
    float* out       = (float*)d_out;
    slayer_kernel<<<2 * (NN / BI), TPB>>>(adj, s, out);
}

// round 10
// speedup vs baseline: 2.6431x; 2.6431x over previous
#include <cuda_runtime.h>
#include <cuda_bf16.h>
#include <stdint.h>
#include <string.h>

#define NN 4096
#define DD 70
#define SSTR 72               // padded row length (floats) in partial buffer
#define KC 64                 // K per chunk
#define KHALF 2048
#define NCH 32                // chunks per CTA (K-half)
#define MTILE 128
#define TPB 256

// SMEM tiles: row stride 144 B (72 bf16) -> 36 banks === 4 (mod 32): conflict-free
#define A_BYTES   (128 * 144)              // 18432 per matrix (hi or lo)
#define B_BYTES   (72 * 144)               // 10368 per matrix
#define STAGE_BYTES (2 * A_BYTES + 2 * B_BYTES)   // 57600
#define SM_AHI(st) ((st) * STAGE_BYTES)
#define SM_ALO(st) (SM_AHI(st) + A_BYTES)
#define SM_BHI(st) (SM_AHI(st) + 2 * A_BYTES)
#define SMEM_TOTAL (2 * STAGE_BYTES)       // 115200

#define B_IMG_BYTES (2 * B_BYTES)          // 20736 per chunk (hi || lo)
#define B_VEC16     (B_IMG_BYTES / 16)     // 1296

// ---- device scratch (no allocs allowed) ----
__device__ __align__(16) unsigned char g_sb[64 * B_IMG_BYTES];   // 1.33 MB, L2-resident
__device__ float g_part[(size_t)2 * 2 * NN * SSTR];              // 9.4 MB partials

// split one fp32 pair into bf16 hi/lo packed b32
__device__ __forceinline__ void split2(float x, float y, uint32_t& h, uint32_t& l) {
    __nv_bfloat162 hh = __floats2bfloat162_rn(x, y);
    float2 hf = __bfloat1622float2(hh);
    __nv_bfloat162 ll = __floats2bfloat162_rn(x - hf.x, y - hf.y);
    h = *reinterpret_cast<uint32_t*>(&hh);
    l = *reinterpret_cast<uint32_t*>(&ll);
}

__device__ __forceinline__ void mma_bf16(float* d, const uint32_t* a, uint32_t b0, uint32_t b1) {
    asm volatile(
        "mma.sync.aligned.m16n8k16.row.col.f32.bf16.bf16.f32 "
        "{%0,%1,%2,%3}, {%4,%5,%6,%7}, {%8,%9}, {%0,%1,%2,%3};"
        : "+f"(d[0]), "+f"(d[1]), "+f"(d[2]), "+f"(d[3])
        : "r"(a[0]), "r"(a[1]), "r"(a[2]), "r"(a[3]), "r"(b0), "r"(b1));
}

// ---------------- kernel 1: per-chunk pre-split B images ----------------
// B[n=d][k] row-major, n in [0,72) (rows >=70 zero), 144B row stride, hi||lo.
__global__ void prep_s_kernel(const float* __restrict__ s) {
    int c  = blockIdx.x;               // chunk 0..63
    int t  = threadIdx.x;              // 576 = 8 kg * 72 d
    int kg = t / SSTR;                 // 0..7 (group of 8 k)
    int d  = t - kg * SSTR;            // 0..71
    float v[8];
#pragma unroll
    for (int m = 0; m < 8; m++) {
        int k = c * KC + kg * 8 + m;
        v[m] = (d < DD) ? s[(size_t)k * DD + d] : 0.0f;
    }
    uint32_t uh[4], ul[4];
#pragma unroll
    for (int j = 0; j < 4; j++) split2(v[2 * j], v[2 * j + 1], uh[j], ul[j]);
    size_t off = (size_t)c * B_IMG_BYTES + d * 144 + kg * 16;
    *(uint4*)(g_sb + off)           = *(const uint4*)uh;
    *(uint4*)(g_sb + off + B_BYTES) = *(const uint4*)ul;
}

// ---------------- kernel 2: split-bf16 mma.sync GEMM, K-split ----------------
// block b: dir = b>>6 (0: s_out row-major A, 1: s_in transposed A),
//          half = (b>>5)&1 (K half), mt = b&31 (128-row tile)
__global__ __launch_bounds__(TPB, 1)
void slayer_mma_kernel(const float* __restrict__ adj)
{
    extern __shared__ unsigned char smem[];
    const int tid  = threadIdx.x;
    const int wid  = tid >> 5;
    const int lane = tid & 31;
    const int b    = blockIdx.x;
    const int dir  = b >> 6;
    const int half = (b >> 5) & 1;
    const int mt   = b & 31;
    const int rowbase = mt * MTILE;
    const int kbase   = half * KHALF;
    const int cbase   = half * NCH;        // global chunk base for B images (R8 fix)
    const bool trans  = (dir == 1);

    const int r4 = lane >> 2;   // 0..7
    const int q4 = lane & 3;    // 0..3

    float acc[9][4];
#pragma unroll
    for (int nt = 0; nt < 9; nt++)
#pragma unroll
        for (int u = 0; u < 4; u++) acc[nt][u] = 0.0f;

    float praw[64];      // prefetched adj values (one chunk slice per thread)
    uint4 pbr[6];        // prefetched B image

    // ---- helpers as macros (keep everything in registers) ----
#define PREFETCH_A(cg)                                                          \
    do {                                                                        \
        int kc_ = kbase + (cg) * KC;                                            \
        if (!trans) {                                                           \
            _Pragma("unroll")                                                   \
            for (int it = 0; it < 4; it++) {                                    \
                int g = tid + it * TPB;                                         \
                int i_l = g >> 3, kg = g & 7;                                   \
                const float4* p = (const float4*)(adj +                         \
                    ((size_t)(rowbase + i_l) * NN + (size_t)(kc_ + kg * 8)) * 2);\
                _Pragma("unroll")                                               \
                for (int u = 0; u < 4; u++) {                                   \
                    float4 v = p[u];                                            \
                    praw[it * 16 + u * 4 + 0] = v.x;                            \
                    praw[it * 16 + u * 4 + 1] = v.y;                            \
                    praw[it * 16 + u * 4 + 2] = v.z;                            \
                    praw[it * 16 + u * 4 + 3] = v.w;                            \
                }                                                               \
            }                                                                   \
        } else {                                                                \
            _Pragma("unroll")                                                   \
            for (int it = 0; it < 4; it++) {                                    \
                int bb = wid + it * 8;                                          \
                int j_l = (bb & 3) * 32 + lane;                                 \
                int i0  = (bb >> 2) * 8;                                        \
                _Pragma("unroll")                                               \
                for (int r = 0; r < 8; r++) {                                   \
                    float2 q = *(const float2*)(adj +                           \
                        ((size_t)(kc_ + i0 + r) * NN + (size_t)(rowbase + j_l)) * 2);\
                    praw[it * 16 + 2 * r]     = q.x;                            \
                    praw[it * 16 + 2 * r + 1] = q.y;                            \
                }                                                               \
            }                                                                   \
        }                                                                       \
    } while (0)

#define PREFETCH_B(cg)                                                          \
    do {                                                                        \
        const unsigned char* bs_ =                                              \
            g_sb + (size_t)(cbase + (cg)) * B_IMG_BYTES;                        \
        _Pragma("unroll")                                                       \
        for (int u = 0; u < 6; u++) {                                           \
            int t2 = tid + u * TPB;                                             \
            if (t2 < B_VEC16) pbr[u] = *(const uint4*)(bs_ + (size_t)t2 * 16);  \
        }                                                                       \
    } while (0)

#define STORE_STAGE(nst)                                                        \
    do {                                                                        \
        _Pragma("unroll")                                                       \
        for (int it = 0; it < 4; it++) {                                        \
            float vs[8];                                                        \
            _Pragma("unroll")                                                   \
            for (int m = 0; m < 8; m++)                                         \
                vs[m] = praw[it * 16 + 2 * m] + praw[it * 16 + 2 * m + 1];      \
            uint32_t uh[4], ul[4];                                              \
            _Pragma("unroll")                                                   \
            for (int j = 0; j < 4; j++) split2(vs[2 * j], vs[2 * j + 1], uh[j], ul[j]);\
            uint32_t off;                                                       \
            if (!trans) {                                                       \
                int g = tid + it * TPB;                                         \
                int i_l = g >> 3, kg = g & 7;                                   \
                off = (uint32_t)(i_l * 144 + kg * 16);                          \
            } else {                                                            \
                int bb = wid + it * 8;                                          \
                int j_l = (bb & 3) * 32 + lane;                                 \
                int i0  = (bb >> 2) * 8;                                        \
                off = (uint32_t)(j_l * 144 + i0 * 2);                           \
            }                                                                   \
            *(uint4*)(smem + SM_AHI(nst) + off) = *(const uint4*)uh;            \
            *(uint4*)(smem + SM_ALO(nst) + off) = *(const uint4*)ul;            \
        }                                                                       \
        _Pragma("unroll")                                                       \
        for (int u = 0; u < 6; u++) {                                           \
            int t2 = tid + u * TPB;                                             \
            if (t2 < B_VEC16)                                                   \
                *(uint4*)(smem + SM_BHI(nst) + (size_t)t2 * 16) = pbr[u];       \
        }                                                                       \
    } while (0)

    // ---- prologue: fill stage 0 with chunk 0 ----
    PREFETCH_A(0);
    PREFETCH_B(0);
    STORE_STAGE(0);
    __syncthreads();

    const uint32_t a_lane = (uint32_t)((wid * 16 + r4) * 144 + q4 * 4);
    const uint32_t b_lane = (uint32_t)(r4 * 144 + q4 * 4);

    for (int c = 0; c < NCH; c++) {
        const int cur = c & 1;
        if (c + 1 < NCH) { PREFETCH_A(c + 1); PREFETCH_B(c + 1); }

        // ---- MMA on stage cur: 4 k-tiles x 9 n-tiles x 3 products ----
        const uint32_t ahb = SM_AHI(cur) + a_lane;
        const uint32_t bhb = SM_BHI(cur) + b_lane;
#pragma unroll
        for (int kt = 0; kt < 4; kt++) {
            uint32_t ao = ahb + kt * 32;
            uint32_t ah[4], al[4];
            ah[0] = *(const uint32_t*)(smem + ao);
            ah[1] = *(const uint32_t*)(smem + ao + 8 * 144);
            ah[2] = *(const uint32_t*)(smem + ao + 16);
            ah[3] = *(const uint32_t*)(smem + ao + 8 * 144 + 16);
            al[0] = *(const uint32_t*)(smem + ao + A_BYTES);
            al[1] = *(const uint32_t*)(smem + ao + A_BYTES + 8 * 144);
            al[2] = *(const uint32_t*)(smem + ao + A_BYTES + 16);
            al[3] = *(const uint32_t*)(smem + ao + A_BYTES + 8 * 144 + 16);
#pragma unroll
            for (int nt = 0; nt < 9; nt++) {
                uint32_t bo = bhb + nt * (8 * 144) + kt * 32;
                uint32_t bh0 = *(const uint32_t*)(smem + bo);
                uint32_t bh1 = *(const uint32_t*)(smem + bo + 16);
                uint32_t bl0 = *(const uint32_t*)(smem + bo + B_BYTES);
                uint32_t bl1 = *(const uint32_t*)(smem + bo + B_BYTES + 16);
                mma_bf16(acc[nt], ah, bh0, bh1);
                mma_bf16(acc[nt], al, bh0, bh1);
                mma_bf16(acc[nt], ah, bl0, bl1);
            }
        }
        __syncthreads();
        if (c + 1 < NCH) STORE_STAGE((c + 1) & 1);
        __syncthreads();
    }

    // ---- epilogue: write partials (row stride SSTR, padded) ----
    float* pb = g_part +
        (((size_t)(dir * 2 + half) * NN) + rowbase + wid * 16 + r4) * SSTR + q4 * 2;
#pragma unroll
    for (int nt = 0; nt < 9; nt++) {
        *(float2*)(pb + nt * 8)             = make_float2(acc[nt][0], acc[nt][1]);
        *(float2*)(pb + 8 * SSTR + nt * 8)  = make_float2(acc[nt][2], acc[nt][3]);
    }
#undef PREFETCH_A
#undef PREFETCH_B
#undef STORE_STAGE
}

// ---------------- kernel 3: sum K-halves, write (s_in, s_out) ----------------
__global__ void reduce_kernel(float* __restrict__ out) {
    int e = blockIdx.x * blockDim.x + threadIdx.x;
    if (e >= 2 * NN * DD) return;
    int dirr = e / (NN * DD);
    int rem  = e - dirr * NN * DD;
    int row  = rem / DD;
    int dcol = rem - row * DD;
    const float* p = g_part + ((size_t)(dirr * 2) * NN + row) * SSTR + dcol;
    float v = p[0] + p[(size_t)NN * SSTR];
    size_t ob = (dirr == 1) ? 0 : (size_t)NN * DD;   // dir 1 (trans) = s_in first
    out[ob + (size_t)row * DD + dcol] = v;
}

extern "C" void kernel_launch(void* const* d_in, const int* in_sizes, int n_in,
                              void* d_out, int out_size)
{
    const float* adj = (const float*)d_in[0];
    const float* s   = (const float*)d_in[1];
    float* out       = (float*)d_out;

    static bool attr_done = false;
    if (!attr_done) {
        cudaFuncSetAttribute(slayer_mma_kernel,
                             cudaFuncAttributeMaxDynamicSharedMemorySize, SMEM_TOTAL);
        attr_done = true;
    }

    prep_s_kernel<<<64, SSTR * 8>>>(s);
    slayer_mma_kernel<<<128, TPB, SMEM_TOTAL>>>(adj);
    reduce_kernel<<<(2 * NN * DD + TPB - 1) / TPB, TPB>>>(out);
}